// round 15
// baseline (speedup 1.0000x reference)
#include <cuda_runtime.h>
#include <cuda_fp16.h>
#include <math.h>
#include <stdint.h>

#define NN    20000
#define KK    16
#define DD    256
#define VV    64
#define KDIM  320
#define MT    157
#define MROWS (MT * 128)

#define RPAD 144                  // smem row stride bytes (72 fp16)

// gemm_h smem (per buffer): A(128 rows) + B1(64 rows)
#define A_OA  0
#define A_OB  18432
#define A_BUF 27648
#define SMEM_A (2 * A_BUF)
// gemm_kld smem: A + B2 + B3
#define B_OA  0
#define B_O2  18432
#define B_O3  27648
#define B_BUF 36864
#define SMEM_B (2 * B_BUF)

// prologue grid partition
#define PB_CONV 2500              // NN*DD/8 / 256 (2 float4 per thread)
#define PB_WB   960               // 320 x 3
#define PB_C    2500              // NN / 8

#define KLD_BLOCKS (4 * MT)       // 628

// ---------------- scratch -------------------------------------------------------
__device__ __align__(16) __half g_A16[MROWS * KDIM];        // fp16 A (gather + C cols)
__device__ __align__(16) __half g_B16[3][DD * KDIM];        // B transposed [n][k], fp16
__device__ __align__(16) __half g_X16[NN * DD];             // fp16 gather source
__device__ float g_partials[1024];
__device__ unsigned g_cnt;

// ---------------- helpers -------------------------------------------------------
__device__ __forceinline__ uint32_t smem_u32(const void* p) {
    uint32_t a;
    asm("{ .reg .u64 t; cvta.to.shared.u64 t, %1; cvt.u32.u64 %0, t; }" : "=r"(a) : "l"(p));
    return a;
}
__device__ __forceinline__ float ex2f(float x) {        // 2^x via MUFU.EX2
    float r;
    asm("ex2.approx.f32 %0, %1;" : "=f"(r) : "f"(x));
    return r;
}
__device__ __forceinline__ float rcpf(float x) {        // 1/x via MUFU.RCP
    float r;
    asm("rcp.approx.f32 %0, %1;" : "=f"(r) : "f"(x));
    return r;
}
#define LOG2E 1.4426950408889634f
__device__ __forceinline__ float fast_tanh(float x) {
    // tanh(x) = 1 - 2/(e^{2x}+1);  e^{2x} = 2^(2x*log2e)
    const float E = ex2f(2.f * LOG2E * x);
    return 1.f - 2.f * rcpf(E + 1.f);
}
__device__ __forceinline__ float fast_exp2t(float t) {  // e^{2t}
    return ex2f(2.f * LOG2E * t);
}
#define CP16(sa, ga) asm volatile("cp.async.ca.shared.global [%0], [%1], 16;" :: "r"(sa), "l"(ga))
#define CP_COMMIT()  asm volatile("cp.async.commit_group;" ::: "memory")
#define CP_WAIT0()   asm volatile("cp.async.wait_group 0;" ::: "memory")
#define LDSM_X4(r, a) \
    asm volatile("ldmatrix.sync.aligned.m8n8.x4.shared.b16 {%0,%1,%2,%3}, [%4];" \
        : "=r"((r)[0]), "=r"((r)[1]), "=r"((r)[2]), "=r"((r)[3]) : "r"(a))
#define LDSM_X2(r, a) \
    asm volatile("ldmatrix.sync.aligned.m8n8.x2.shared.b16 {%0,%1}, [%2];" \
        : "=r"((r)[0]), "=r"((r)[1]) : "r"(a))
#define MMA_F16(d, a, b) \
    asm volatile("mma.sync.aligned.m16n8k16.row.col.f32.f16.f16.f32 " \
        "{%0,%1,%2,%3}, {%4,%5,%6,%7}, {%8,%9}, {%0,%1,%2,%3};" \
        : "+f"((d)[0]), "+f"((d)[1]), "+f"((d)[2]), "+f"((d)[3]) \
        : "r"((a)[0]), "r"((a)[1]), "r"((a)[2]), "r"((a)[3]), "r"((b)[0]), "r"((b)[1]))

// ---------------- 0) fused prologue: conv16 | prep_wb | compute_c ----------------
__global__ void prep_all(const float* __restrict__ src,
                         const float* __restrict__ W1, const float* __restrict__ E1,
                         const float* __restrict__ W2, const float* __restrict__ E2,
                         const float* __restrict__ W3, const float* __restrict__ E3,
                         const int* __restrict__ ie, const float* __restrict__ im,
                         const int* __restrict__ oe, const float* __restrict__ om)
{
    const int b = blockIdx.x;
    const int tid = threadIdx.x;

    if (b == 0 && tid == 0) g_cnt = 0;      // reset kld completion counter

    if (b < PB_CONV) {
        #pragma unroll
        for (int h = 0; h < 2; h++) {
            const int i = b * 512 + h * 256 + tid;
            const float4 v = ((const float4*)src)[i];
            const __half2 a2 = __floats2half2_rn(v.x, v.y);
            const __half2 b2 = __floats2half2_rn(v.z, v.w);
            uint2 u; u.x = *(const uint32_t*)&a2; u.y = *(const uint32_t*)&b2;
            ((uint2*)g_X16)[i] = u;
        }
        return;
    }
    if (b < PB_CONV + PB_WB) {
        const int rb = b - PB_CONV;
        const int r = rb % KDIM;
        const int l = rb / KDIM;
        const int d = tid;
        const float* W = (l == 0) ? W1 : (l == 1) ? W2 : W3;
        const float* E = (l == 0) ? E1 : (l == 1) ? E2 : E3;
        float x;
        if (r < DD) {
            x = W[r * DD + d];
        } else {
            const int v = r - DD;
            __shared__ float sE[DD];
            sE[d] = E[v * DD + d];
            __syncthreads();
            float acc = 0.f;
            #pragma unroll 8
            for (int j = 0; j < DD; j++) acc += sE[j] * W[(DD + j) * DD + d];
            x = acc;
        }
        g_B16[l][d * KDIM + r] = __float2half_rn(x);
        return;
    }
    const int warp = tid >> 5;
    const int lane = tid & 31;
    const int n = (b - PB_CONV - PB_WB) * 8 + warp;
    if (n >= NN) return;

    int e; float m;
    if (lane < KK) { e = ie[n * KK + lane];      m = im[n * KK + lane]; }
    else           { e = oe[n * KK + lane - KK]; m = om[n * KK + lane - KK]; }

    float c0 = 0.f, c1 = 0.f;
    #pragma unroll
    for (int s = 0; s < 32; s++) {
        const int   ev = __shfl_sync(0xFFFFFFFFu, e, s);
        const float mv = __shfl_sync(0xFFFFFFFFu, m, s);
        if (ev == lane)      c0 += mv;
        if (ev == lane + 32) c1 += mv;
    }
    g_A16[n * KDIM + DD + lane]      = __float2half_rn(c0);
    g_A16[n * KDIM + DD + 32 + lane] = __float2half_rn(c1);
}

// ---------------- 1) fp16 gather-sum -> fp16 A (deep-MLP unroll) ------------------
__global__ void gather16(const int*   __restrict__ ii, const float* __restrict__ imk,
                         const int*   __restrict__ oi, const float* __restrict__ omk)
{
    const int warp = threadIdx.x >> 5;
    const int lane = threadIdx.x & 31;
    const int n = blockIdx.x * 8 + warp;
    if (n >= NN) return;

    int e; float m;
    if (lane < KK) { e = ii[n * KK + lane];      m = imk[n * KK + lane]; }
    else           { e = oi[n * KK + lane - KK]; m = omk[n * KK + lane - KK]; }

    float acc[8];
    #pragma unroll
    for (int j = 0; j < 8; j++) acc[j] = 0.f;

    #pragma unroll 16
    for (int k = 0; k < 32; k++) {
        const int   id = __shfl_sync(0xFFFFFFFFu, e, k);
        const float mm = __shfl_sync(0xFFFFFFFFu, m, k);
        const uint4 v = __ldg((const uint4*)(g_X16 + (size_t)id * DD + lane * 8));
        const __half2* hp = (const __half2*)&v;
        #pragma unroll
        for (int j = 0; j < 4; j++) {
            const float2 f = __half22float2(hp[j]);
            acc[2 * j]     += mm * f.x;
            acc[2 * j + 1] += mm * f.y;
        }
    }
    __half hb[8];
    #pragma unroll
    for (int j = 0; j < 8; j++) hb[j] = __float2half_rn(acc[j]);
    *(uint4*)(g_A16 + (size_t)n * KDIM + lane * 8) = *(const uint4*)hb;
}

// ---------------- 2a) GEMM hidden: CTA 128x64, single fp16 B ----------------------
__global__ __launch_bounds__(256, 3)
void gemm_h(const float* __restrict__ base,
            const float* __restrict__ bias,
            float* __restrict__ out)
{
    extern __shared__ char smc[];
    const uint32_t sb = smem_u32(smc);

    const int tid  = threadIdx.x;
    const int lane = tid & 31;
    const int wid  = tid >> 5;
    const int mw   = wid >> 1;
    const int nw   = wid & 1;
    const int m0   = blockIdx.x * 128;
    const int nb0  = blockIdx.y * 64;

    const __half* __restrict__ B1 = g_B16[0];

    auto load_chunk = [&](int c, int bsel) {
        const uint32_t s0 = sb + bsel * A_BUF;
        #pragma unroll
        for (int it = 0; it < 4; it++) {
            const int i = tid + it * 256;
            const int row = i >> 3, u = i & 7;
            CP16(s0 + A_OA + row * RPAD + u * 16,
                 g_A16 + (size_t)(m0 + row) * KDIM + c * 64 + u * 8);
        }
        #pragma unroll
        for (int it = 0; it < 2; it++) {
            const int i = tid + it * 256;
            const int row = i >> 3, u = i & 7;
            CP16(s0 + A_OB + row * RPAD + u * 16,
                 B1 + (size_t)(nb0 + row) * KDIM + c * 64 + u * 8);
        }
        CP_COMMIT();
    };

    float acc[2][4][4];
    #pragma unroll
    for (int i = 0; i < 2; i++)
        #pragma unroll
        for (int j = 0; j < 4; j++)
            #pragma unroll
            for (int f = 0; f < 4; f++) acc[i][j][f] = 0.f;

    load_chunk(0, 0);
    CP_WAIT0();
    __syncthreads();

    const uint32_t a_rb = (mw * 32 + (lane & 15)) * RPAD + (lane >> 4) * 16;
    const uint32_t b_rb = (nw * 32 + (lane & 7)) * RPAD + ((lane >> 3) & 1) * 16;

    for (int c = 0; c < 5; c++) {
        if (c + 1 < 5) load_chunk(c + 1, (c + 1) & 1);
        const uint32_t bufs = sb + (c & 1) * A_BUF;

        #pragma unroll
        for (int s = 0; s < 4; s++) {
            uint32_t bh[4][2];
            #pragma unroll
            for (int ni = 0; ni < 4; ni++)
                LDSM_X2(bh[ni], bufs + A_OB + b_rb + ni * (8 * RPAD) + s * 32);
            #pragma unroll
            for (int mi = 0; mi < 2; mi++) {
                uint32_t a[4];
                LDSM_X4(a, bufs + A_OA + a_rb + mi * (16 * RPAD) + s * 32);
                #pragma unroll
                for (int ni = 0; ni < 4; ni++)
                    MMA_F16(acc[mi][ni], a, bh[ni]);
            }
        }
        if (c + 1 < 5) { CP_WAIT0(); __syncthreads(); }
    }

    const int g  = lane >> 2;
    const int q2 = (lane & 3) * 2;
    #pragma unroll
    for (int mi = 0; mi < 2; mi++) {
        const int r0 = m0 + mw * 32 + mi * 16 + g;
        #pragma unroll
        for (int ni = 0; ni < 4; ni++) {
            const int cc = nb0 + nw * 32 + ni * 8 + q2;
            const float2 bv = *(const float2*)(bias + cc);
            #pragma unroll
            for (int h = 0; h < 2; h++) {
                const int r = r0 + h * 8;
                if (r < NN) {
                    const float2 b0 = *(const float2*)(base + (size_t)r * DD + cc);
                    float2 o;
                    o.x = b0.x + acc[mi][ni][2 * h + 0] + 2.f * bv.x;
                    o.y = b0.y + acc[mi][ni][2 * h + 1] + 2.f * bv.y;
                    *(float2*)(out + (size_t)r * DD + cc) = o;
                    const __half2 h2 = __floats2half2_rn(o.x, o.y);
                    *(uint32_t*)(g_X16 + (size_t)r * DD + cc) = *(const uint32_t*)&h2;
                }
            }
        }
    }
}

// ---------------- 2b) fused mu+logvar GEMM + last-CTA kld finalize ----------------
__global__ __launch_bounds__(256)
void gemm_kld(const float* __restrict__ base,
              const float* __restrict__ b2, const float* __restrict__ b3,
              float* __restrict__ out_kld, int write_kld)
{
    extern __shared__ char smc[];
    const uint32_t sb = smem_u32(smc);

    const int tid  = threadIdx.x;
    const int lane = tid & 31;
    const int wid  = tid >> 5;
    const int mw   = wid >> 1;
    const int nw   = wid & 1;
    const int m0   = blockIdx.x * 128;
    const int nb0  = blockIdx.y * 64;

    auto load_chunk = [&](int c, int bsel) {
        const uint32_t s0 = sb + bsel * B_BUF;
        #pragma unroll
        for (int it = 0; it < 4; it++) {
            const int i = tid + it * 256;
            const int row = i >> 3, u = i & 7;
            CP16(s0 + B_OA + row * RPAD + u * 16,
                 g_A16 + (size_t)(m0 + row) * KDIM + c * 64 + u * 8);
        }
        #pragma unroll
        for (int it = 0; it < 2; it++) {
            const int i = tid + it * 256;
            const int row = i >> 3, u = i & 7;
            const size_t go = (size_t)(nb0 + row) * KDIM + c * 64 + u * 8;
            const uint32_t so = row * RPAD + u * 16;
            CP16(s0 + B_O2 + so, g_B16[1] + go);
            CP16(s0 + B_O3 + so, g_B16[2] + go);
        }
        CP_COMMIT();
    };

    float acc2[2][4][4], acc3[2][4][4];
    #pragma unroll
    for (int i = 0; i < 2; i++)
        #pragma unroll
        for (int j = 0; j < 4; j++)
            #pragma unroll
            for (int f = 0; f < 4; f++) { acc2[i][j][f] = 0.f; acc3[i][j][f] = 0.f; }

    load_chunk(0, 0);
    CP_WAIT0();
    __syncthreads();

    const uint32_t a_rb = (mw * 32 + (lane & 15)) * RPAD + (lane >> 4) * 16;
    const uint32_t b_rb = (nw * 32 + (lane & 7)) * RPAD + ((lane >> 3) & 1) * 16;

    for (int c = 0; c < 5; c++) {
        if (c + 1 < 5) load_chunk(c + 1, (c + 1) & 1);
        const uint32_t bufs = sb + (c & 1) * B_BUF;

        #pragma unroll
        for (int s = 0; s < 4; s++) {
            uint32_t v2[4][2], v3[4][2];
            #pragma unroll
            for (int ni = 0; ni < 4; ni++) {
                const uint32_t bd = bufs + b_rb + ni * (8 * RPAD) + s * 32;
                LDSM_X2(v2[ni], bd + B_O2);
                LDSM_X2(v3[ni], bd + B_O3);
            }
            #pragma unroll
            for (int mi = 0; mi < 2; mi++) {
                uint32_t a[4];
                LDSM_X4(a, bufs + B_OA + a_rb + mi * (16 * RPAD) + s * 32);
                #pragma unroll
                for (int ni = 0; ni < 4; ni++) {
                    MMA_F16(acc2[mi][ni], a, v2[ni]);
                    MMA_F16(acc3[mi][ni], a, v3[ni]);
                }
            }
        }
        if (c + 1 < 5) { CP_WAIT0(); __syncthreads(); }
    }

    const int g  = lane >> 2;
    const int q2 = (lane & 3) * 2;
    float smu = 0.f, slv = 0.f;
    #pragma unroll
    for (int mi = 0; mi < 2; mi++) {
        const int r0 = m0 + mw * 32 + mi * 16 + g;
        #pragma unroll
        for (int ni = 0; ni < 4; ni++) {
            const int cc = nb0 + nw * 32 + ni * 8 + q2;
            const float2 w2 = *(const float2*)(b2 + cc);
            const float2 w3 = *(const float2*)(b3 + cc);
            #pragma unroll
            for (int h = 0; h < 2; h++) {
                const int r = r0 + h * 8;
                if (r < NN) {
                    const float2 b0 = *(const float2*)(base + (size_t)r * DD + cc);
                    const float xm0 = b0.x + acc2[mi][ni][2 * h + 0] + 2.f * w2.x;
                    const float xm1 = b0.y + acc2[mi][ni][2 * h + 1] + 2.f * w2.y;
                    const float xl0 = b0.x + acc3[mi][ni][2 * h + 0] + 2.f * w3.x;
                    const float xl1 = b0.y + acc3[mi][ni][2 * h + 1] + 2.f * w3.y;
                    const float tm0 = fast_tanh(xm0), tm1 = fast_tanh(xm1);
                    const float tl0 = fast_tanh(xl0), tl1 = fast_tanh(xl1);
                    smu -= tm0 * tm0 + tm1 * tm1;
                    slv += 2.f + 2.f * (tl0 + tl1) - fast_exp2t(tl0) - fast_exp2t(tl1);
                }
            }
        }
    }

    __syncthreads();
    float* red = (float*)smc;
    red[tid] = smu;
    red[256 + tid] = slv;
    __syncthreads();
    #pragma unroll
    for (int o = 128; o > 0; o >>= 1) {
        if (tid < o) { red[tid] += red[tid + o]; red[256 + tid] += red[256 + tid + o]; }
        __syncthreads();
    }

    __shared__ unsigned s_last;
    if (tid == 0) {
        g_partials[blockIdx.y * gridDim.x + blockIdx.x] = red[0] + red[256];
        __threadfence();
        s_last = (atomicAdd(&g_cnt, 1u) == KLD_BLOCKS - 1);
    }
    __syncthreads();

    if (s_last && write_kld) {
        __threadfence();
        double* dred = (double*)smc;
        double s = 0.0;
        for (int i = tid; i < KLD_BLOCKS; i += 256) s += (double)g_partials[i];
        dred[tid] = s;
        __syncthreads();
        #pragma unroll
        for (int o = 128; o > 0; o >>= 1) {
            if (tid < o) dred[tid] += dred[tid + o];
            __syncthreads();
        }
        if (tid == 0)
            out_kld[0] = (float)(-0.5 * dred[0] / ((double)NN * (double)NN));
    }
}

// ---------------- launch ------------------------------------------------------------
extern "C" void kernel_launch(void* const* d_in, const int* in_sizes, int n_in,
                              void* d_out, int out_size)
{
    const float* node_reps = (const float*)d_in[0];
    const int*   in_idx    = (const int*)  d_in[1];
    const int*   in_edg    = (const int*)  d_in[2];
    const float* in_msk    = (const float*)d_in[3];
    const int*   out_idx   = (const int*)  d_in[4];
    const int*   out_edg   = (const int*)  d_in[5];
    const float* out_msk   = (const float*)d_in[6];
    const float* E1 = (const float*)d_in[7];
    const float* W1 = (const float*)d_in[8];
    const float* b1 = (const float*)d_in[9];
    const float* E2 = (const float*)d_in[10];
    const float* W2 = (const float*)d_in[11];
    const float* b2 = (const float*)d_in[12];
    const float* E3 = (const float*)d_in[13];
    const float* W3 = (const float*)d_in[14];
    const float* b3 = (const float*)d_in[15];

    float* hidden = (float*)d_out;
    float* kld_out = hidden + (size_t)NN * DD;
    const int write_kld = (out_size > NN * DD) ? 1 : 0;

    cudaFuncSetAttribute(gemm_h,   cudaFuncAttributeMaxDynamicSharedMemorySize, SMEM_A);
    cudaFuncSetAttribute(gemm_kld, cudaFuncAttributeMaxDynamicSharedMemorySize, SMEM_B);

    const dim3 gg(MT, 4);   // 628 CTAs, N tile 64

    prep_all<<<PB_CONV + PB_WB + PB_C, 256>>>(node_reps, W1, E1, W2, E2, W3, E3,
                                              in_edg, in_msk, out_edg, out_msk);

    gather16<<<(NN + 7) / 8, 256>>>(in_idx, in_msk, out_idx, out_msk);
    gemm_h<<<gg, 256, SMEM_A>>>(node_reps, b1, hidden);

    gather16<<<(NN + 7) / 8, 256>>>(in_idx, in_msk, out_idx, out_msk);
    gemm_kld<<<gg, 256, SMEM_B>>>(hidden, b2, b3, kld_out, write_kld);
}

// round 16
// speedup vs baseline: 1.0257x; 1.0257x over previous
#include <cuda_runtime.h>
#include <cuda_fp16.h>
#include <math.h>
#include <stdint.h>

#define NN    20000
#define KK    16
#define DD    256
#define VV    64
#define KDIM  320
#define MT    157
#define MROWS (MT * 128)

#define RPAD 144                  // smem row stride bytes (72 fp16)

// gemm_h smem (per buffer): A(128 rows) + B1(64 rows)
#define A_OA  0
#define A_OB  18432
#define A_BUF 27648
#define SMEM_A (2 * A_BUF)
// gemm_kld smem: A + B2 + B3
#define B_OA  0
#define B_O2  18432
#define B_O3  27648
#define B_BUF 36864
#define SMEM_B (2 * B_BUF)

// prologue grid partition
#define PB_CONV 2500              // NN*DD/8 / 256 (2 float4 per thread)
#define PB_WB   960               // 320 x 3
#define PB_C    2500              // NN / 8

#define KLD_BLOCKS (4 * MT)       // 628

// ---------------- scratch -------------------------------------------------------
__device__ __align__(16) __half g_A16[MROWS * KDIM];        // fp16 A (gather + C cols)
__device__ __align__(16) __half g_B16[3][DD * KDIM];        // B transposed [n][k], fp16
__device__ __align__(16) __half g_X16[NN * DD];             // fp16 gather source
__device__ float g_partials[1024];
__device__ unsigned g_cnt;

// ---------------- helpers -------------------------------------------------------
__device__ __forceinline__ uint32_t smem_u32(const void* p) {
    uint32_t a;
    asm("{ .reg .u64 t; cvta.to.shared.u64 t, %1; cvt.u32.u64 %0, t; }" : "=r"(a) : "l"(p));
    return a;
}
__device__ __forceinline__ float ex2f(float x) {        // 2^x via MUFU.EX2
    float r;
    asm("ex2.approx.f32 %0, %1;" : "=f"(r) : "f"(x));
    return r;
}
__device__ __forceinline__ float rcpf(float x) {        // 1/x via MUFU.RCP
    float r;
    asm("rcp.approx.f32 %0, %1;" : "=f"(r) : "f"(x));
    return r;
}
#define LOG2E 1.4426950408889634f
__device__ __forceinline__ float fast_tanh(float x) {
    // tanh(x) = 1 - 2/(e^{2x}+1);  e^{2x} = 2^(2x*log2e)
    const float E = ex2f(2.f * LOG2E * x);
    return 1.f - 2.f * rcpf(E + 1.f);
}
__device__ __forceinline__ float fast_exp2t(float t) {  // e^{2t}
    return ex2f(2.f * LOG2E * t);
}
#define CP16(sa, ga) asm volatile("cp.async.ca.shared.global [%0], [%1], 16;" :: "r"(sa), "l"(ga))
#define CP_COMMIT()  asm volatile("cp.async.commit_group;" ::: "memory")
#define CP_WAIT0()   asm volatile("cp.async.wait_group 0;" ::: "memory")
#define LDSM_X4(r, a) \
    asm volatile("ldmatrix.sync.aligned.m8n8.x4.shared.b16 {%0,%1,%2,%3}, [%4];" \
        : "=r"((r)[0]), "=r"((r)[1]), "=r"((r)[2]), "=r"((r)[3]) : "r"(a))
#define LDSM_X2(r, a) \
    asm volatile("ldmatrix.sync.aligned.m8n8.x2.shared.b16 {%0,%1}, [%2];" \
        : "=r"((r)[0]), "=r"((r)[1]) : "r"(a))
#define MMA_F16(d, a, b) \
    asm volatile("mma.sync.aligned.m16n8k16.row.col.f32.f16.f16.f32 " \
        "{%0,%1,%2,%3}, {%4,%5,%6,%7}, {%8,%9}, {%0,%1,%2,%3};" \
        : "+f"((d)[0]), "+f"((d)[1]), "+f"((d)[2]), "+f"((d)[3]) \
        : "r"((a)[0]), "r"((a)[1]), "r"((a)[2]), "r"((a)[3]), "r"((b)[0]), "r"((b)[1]))

// ---------------- 0) fused prologue: conv16 | prep_wb | compute_c ----------------
__global__ void prep_all(const float* __restrict__ src,
                         const float* __restrict__ W1, const float* __restrict__ E1,
                         const float* __restrict__ W2, const float* __restrict__ E2,
                         const float* __restrict__ W3, const float* __restrict__ E3,
                         const int* __restrict__ ie, const float* __restrict__ im,
                         const int* __restrict__ oe, const float* __restrict__ om)
{
    const int b = blockIdx.x;
    const int tid = threadIdx.x;

    if (b == 0 && tid == 0) g_cnt = 0;      // reset kld completion counter

    if (b < PB_CONV) {
        #pragma unroll
        for (int h = 0; h < 2; h++) {
            const int i = b * 512 + h * 256 + tid;
            const float4 v = ((const float4*)src)[i];
            const __half2 a2 = __floats2half2_rn(v.x, v.y);
            const __half2 b2 = __floats2half2_rn(v.z, v.w);
            uint2 u; u.x = *(const uint32_t*)&a2; u.y = *(const uint32_t*)&b2;
            ((uint2*)g_X16)[i] = u;
        }
        return;
    }
    if (b < PB_CONV + PB_WB) {
        const int rb = b - PB_CONV;
        const int r = rb % KDIM;
        const int l = rb / KDIM;
        const int d = tid;
        const float* W = (l == 0) ? W1 : (l == 1) ? W2 : W3;
        const float* E = (l == 0) ? E1 : (l == 1) ? E2 : E3;
        float x;
        if (r < DD) {
            x = W[r * DD + d];
        } else {
            const int v = r - DD;
            __shared__ float sE[DD];
            sE[d] = E[v * DD + d];
            __syncthreads();
            float acc = 0.f;
            #pragma unroll 8
            for (int j = 0; j < DD; j++) acc += sE[j] * W[(DD + j) * DD + d];
            x = acc;
        }
        g_B16[l][d * KDIM + r] = __float2half_rn(x);
        return;
    }
    const int warp = tid >> 5;
    const int lane = tid & 31;
    const int n = (b - PB_CONV - PB_WB) * 8 + warp;
    if (n >= NN) return;

    int e; float m;
    if (lane < KK) { e = ie[n * KK + lane];      m = im[n * KK + lane]; }
    else           { e = oe[n * KK + lane - KK]; m = om[n * KK + lane - KK]; }

    float c0 = 0.f, c1 = 0.f;
    #pragma unroll
    for (int s = 0; s < 32; s++) {
        const int   ev = __shfl_sync(0xFFFFFFFFu, e, s);
        const float mv = __shfl_sync(0xFFFFFFFFu, m, s);
        if (ev == lane)      c0 += mv;
        if (ev == lane + 32) c1 += mv;
    }
    g_A16[n * KDIM + DD + lane]      = __float2half_rn(c0);
    g_A16[n * KDIM + DD + 32 + lane] = __float2half_rn(c1);
}

// ---------------- 1) fp16 gather-sum -> fp16 A ------------------------------------
__global__ void gather16(const int*   __restrict__ ii, const float* __restrict__ imk,
                         const int*   __restrict__ oi, const float* __restrict__ omk)
{
    const int warp = threadIdx.x >> 5;
    const int lane = threadIdx.x & 31;
    const int n = blockIdx.x * 8 + warp;
    if (n >= NN) return;

    int e; float m;
    if (lane < KK) { e = ii[n * KK + lane];      m = imk[n * KK + lane]; }
    else           { e = oi[n * KK + lane - KK]; m = omk[n * KK + lane - KK]; }

    float acc[8];
    #pragma unroll
    for (int j = 0; j < 8; j++) acc[j] = 0.f;

    #pragma unroll 16
    for (int k = 0; k < 32; k++) {
        const int   id = __shfl_sync(0xFFFFFFFFu, e, k);
        const float mm = __shfl_sync(0xFFFFFFFFu, m, k);
        const uint4 v = __ldg((const uint4*)(g_X16 + (size_t)id * DD + lane * 8));
        const __half2* hp = (const __half2*)&v;
        #pragma unroll
        for (int j = 0; j < 4; j++) {
            const float2 f = __half22float2(hp[j]);
            acc[2 * j]     += mm * f.x;
            acc[2 * j + 1] += mm * f.y;
        }
    }
    __half hb[8];
    #pragma unroll
    for (int j = 0; j < 8; j++) hb[j] = __float2half_rn(acc[j]);
    *(uint4*)(g_A16 + (size_t)n * KDIM + lane * 8) = *(const uint4*)hb;
}

// ---------------- 2a) GEMM hidden: CTA 128x64, single fp16 B ----------------------
__global__ __launch_bounds__(256, 3)
void gemm_h(const float* __restrict__ base,
            const float* __restrict__ bias,
            float* __restrict__ out)
{
    extern __shared__ char smc[];
    const uint32_t sb = smem_u32(smc);

    const int tid  = threadIdx.x;
    const int lane = tid & 31;
    const int wid  = tid >> 5;
    const int mw   = wid >> 1;
    const int nw   = wid & 1;
    const int m0   = blockIdx.x * 128;
    const int nb0  = blockIdx.y * 64;

    const __half* __restrict__ B1 = g_B16[0];

    auto load_chunk = [&](int c, int bsel) {
        const uint32_t s0 = sb + bsel * A_BUF;
        #pragma unroll
        for (int it = 0; it < 4; it++) {
            const int i = tid + it * 256;
            const int row = i >> 3, u = i & 7;
            CP16(s0 + A_OA + row * RPAD + u * 16,
                 g_A16 + (size_t)(m0 + row) * KDIM + c * 64 + u * 8);
        }
        #pragma unroll
        for (int it = 0; it < 2; it++) {
            const int i = tid + it * 256;
            const int row = i >> 3, u = i & 7;
            CP16(s0 + A_OB + row * RPAD + u * 16,
                 B1 + (size_t)(nb0 + row) * KDIM + c * 64 + u * 8);
        }
        CP_COMMIT();
    };

    float acc[2][4][4];
    #pragma unroll
    for (int i = 0; i < 2; i++)
        #pragma unroll
        for (int j = 0; j < 4; j++)
            #pragma unroll
            for (int f = 0; f < 4; f++) acc[i][j][f] = 0.f;

    load_chunk(0, 0);
    CP_WAIT0();
    __syncthreads();

    const uint32_t a_rb = (mw * 32 + (lane & 15)) * RPAD + (lane >> 4) * 16;
    const uint32_t b_rb = (nw * 32 + (lane & 7)) * RPAD + ((lane >> 3) & 1) * 16;

    for (int c = 0; c < 5; c++) {
        if (c + 1 < 5) load_chunk(c + 1, (c + 1) & 1);
        const uint32_t bufs = sb + (c & 1) * A_BUF;

        #pragma unroll
        for (int s = 0; s < 4; s++) {
            uint32_t bh[4][2];
            #pragma unroll
            for (int ni = 0; ni < 4; ni++)
                LDSM_X2(bh[ni], bufs + A_OB + b_rb + ni * (8 * RPAD) + s * 32);
            #pragma unroll
            for (int mi = 0; mi < 2; mi++) {
                uint32_t a[4];
                LDSM_X4(a, bufs + A_OA + a_rb + mi * (16 * RPAD) + s * 32);
                #pragma unroll
                for (int ni = 0; ni < 4; ni++)
                    MMA_F16(acc[mi][ni], a, bh[ni]);
            }
        }
        if (c + 1 < 5) { CP_WAIT0(); __syncthreads(); }
    }

    const int g  = lane >> 2;
    const int q2 = (lane & 3) * 2;
    #pragma unroll
    for (int mi = 0; mi < 2; mi++) {
        const int r0 = m0 + mw * 32 + mi * 16 + g;
        #pragma unroll
        for (int ni = 0; ni < 4; ni++) {
            const int cc = nb0 + nw * 32 + ni * 8 + q2;
            const float2 bv = *(const float2*)(bias + cc);
            #pragma unroll
            for (int h = 0; h < 2; h++) {
                const int r = r0 + h * 8;
                if (r < NN) {
                    const float2 b0 = *(const float2*)(base + (size_t)r * DD + cc);
                    float2 o;
                    o.x = b0.x + acc[mi][ni][2 * h + 0] + 2.f * bv.x;
                    o.y = b0.y + acc[mi][ni][2 * h + 1] + 2.f * bv.y;
                    *(float2*)(out + (size_t)r * DD + cc) = o;
                    const __half2 h2 = __floats2half2_rn(o.x, o.y);
                    *(uint32_t*)(g_X16 + (size_t)r * DD + cc) = *(const uint32_t*)&h2;
                }
            }
        }
    }
}

// ---------------- 2b) fused mu+logvar GEMM + last-CTA kld finalize ----------------
// epilogue reads hidden from the fp16 table (g_X16) — halves base traffic; kld-only.
__global__ __launch_bounds__(256)
void gemm_kld(const float* __restrict__ b2, const float* __restrict__ b3,
              float* __restrict__ out_kld, int write_kld)
{
    extern __shared__ char smc[];
    const uint32_t sb = smem_u32(smc);

    const int tid  = threadIdx.x;
    const int lane = tid & 31;
    const int wid  = tid >> 5;
    const int mw   = wid >> 1;
    const int nw   = wid & 1;
    const int m0   = blockIdx.x * 128;
    const int nb0  = blockIdx.y * 64;

    auto load_chunk = [&](int c, int bsel) {
        const uint32_t s0 = sb + bsel * B_BUF;
        #pragma unroll
        for (int it = 0; it < 4; it++) {
            const int i = tid + it * 256;
            const int row = i >> 3, u = i & 7;
            CP16(s0 + B_OA + row * RPAD + u * 16,
                 g_A16 + (size_t)(m0 + row) * KDIM + c * 64 + u * 8);
        }
        #pragma unroll
        for (int it = 0; it < 2; it++) {
            const int i = tid + it * 256;
            const int row = i >> 3, u = i & 7;
            const size_t go = (size_t)(nb0 + row) * KDIM + c * 64 + u * 8;
            const uint32_t so = row * RPAD + u * 16;
            CP16(s0 + B_O2 + so, g_B16[1] + go);
            CP16(s0 + B_O3 + so, g_B16[2] + go);
        }
        CP_COMMIT();
    };

    float acc2[2][4][4], acc3[2][4][4];
    #pragma unroll
    for (int i = 0; i < 2; i++)
        #pragma unroll
        for (int j = 0; j < 4; j++)
            #pragma unroll
            for (int f = 0; f < 4; f++) { acc2[i][j][f] = 0.f; acc3[i][j][f] = 0.f; }

    load_chunk(0, 0);
    CP_WAIT0();
    __syncthreads();

    const uint32_t a_rb = (mw * 32 + (lane & 15)) * RPAD + (lane >> 4) * 16;
    const uint32_t b_rb = (nw * 32 + (lane & 7)) * RPAD + ((lane >> 3) & 1) * 16;

    for (int c = 0; c < 5; c++) {
        if (c + 1 < 5) load_chunk(c + 1, (c + 1) & 1);
        const uint32_t bufs = sb + (c & 1) * B_BUF;

        #pragma unroll
        for (int s = 0; s < 4; s++) {
            uint32_t v2[4][2], v3[4][2];
            #pragma unroll
            for (int ni = 0; ni < 4; ni++) {
                const uint32_t bd = bufs + b_rb + ni * (8 * RPAD) + s * 32;
                LDSM_X2(v2[ni], bd + B_O2);
                LDSM_X2(v3[ni], bd + B_O3);
            }
            #pragma unroll
            for (int mi = 0; mi < 2; mi++) {
                uint32_t a[4];
                LDSM_X4(a, bufs + B_OA + a_rb + mi * (16 * RPAD) + s * 32);
                #pragma unroll
                for (int ni = 0; ni < 4; ni++) {
                    MMA_F16(acc2[mi][ni], a, v2[ni]);
                    MMA_F16(acc3[mi][ni], a, v3[ni]);
                }
            }
        }
        if (c + 1 < 5) { CP_WAIT0(); __syncthreads(); }
    }

    const int g  = lane >> 2;
    const int q2 = (lane & 3) * 2;
    float smu = 0.f, slv = 0.f;
    #pragma unroll
    for (int mi = 0; mi < 2; mi++) {
        const int r0 = m0 + mw * 32 + mi * 16 + g;
        #pragma unroll
        for (int ni = 0; ni < 4; ni++) {
            const int cc = nb0 + nw * 32 + ni * 8 + q2;
            const float2 w2 = *(const float2*)(b2 + cc);
            const float2 w3 = *(const float2*)(b3 + cc);
            #pragma unroll
            for (int h = 0; h < 2; h++) {
                const int r = r0 + h * 8;
                if (r < NN) {
                    const __half2 hb = *(const __half2*)(g_X16 + (size_t)r * DD + cc);
                    const float2 b0 = __half22float2(hb);
                    const float xm0 = b0.x + acc2[mi][ni][2 * h + 0] + 2.f * w2.x;
                    const float xm1 = b0.y + acc2[mi][ni][2 * h + 1] + 2.f * w2.y;
                    const float xl0 = b0.x + acc3[mi][ni][2 * h + 0] + 2.f * w3.x;
                    const float xl1 = b0.y + acc3[mi][ni][2 * h + 1] + 2.f * w3.y;
                    const float tm0 = fast_tanh(xm0), tm1 = fast_tanh(xm1);
                    const float tl0 = fast_tanh(xl0), tl1 = fast_tanh(xl1);
                    smu -= tm0 * tm0 + tm1 * tm1;
                    slv += 2.f + 2.f * (tl0 + tl1) - fast_exp2t(tl0) - fast_exp2t(tl1);
                }
            }
        }
    }

    __syncthreads();
    float* red = (float*)smc;
    red[tid] = smu;
    red[256 + tid] = slv;
    __syncthreads();
    #pragma unroll
    for (int o = 128; o > 0; o >>= 1) {
        if (tid < o) { red[tid] += red[tid + o]; red[256 + tid] += red[256 + tid + o]; }
        __syncthreads();
    }

    __shared__ unsigned s_last;
    if (tid == 0) {
        g_partials[blockIdx.y * gridDim.x + blockIdx.x] = red[0] + red[256];
        __threadfence();
        s_last = (atomicAdd(&g_cnt, 1u) == KLD_BLOCKS - 1);
    }
    __syncthreads();

    if (s_last && write_kld) {
        __threadfence();
        double* dred = (double*)smc;
        double s = 0.0;
        for (int i = tid; i < KLD_BLOCKS; i += 256) s += (double)g_partials[i];
        dred[tid] = s;
        __syncthreads();
        #pragma unroll
        for (int o = 128; o > 0; o >>= 1) {
            if (tid < o) dred[tid] += dred[tid + o];
            __syncthreads();
        }
        if (tid == 0)
            out_kld[0] = (float)(-0.5 * dred[0] / ((double)NN * (double)NN));
    }
}

// ---------------- launch ------------------------------------------------------------
extern "C" void kernel_launch(void* const* d_in, const int* in_sizes, int n_in,
                              void* d_out, int out_size)
{
    const float* node_reps = (const float*)d_in[0];
    const int*   in_idx    = (const int*)  d_in[1];
    const int*   in_edg    = (const int*)  d_in[2];
    const float* in_msk    = (const float*)d_in[3];
    const int*   out_idx   = (const int*)  d_in[4];
    const int*   out_edg   = (const int*)  d_in[5];
    const float* out_msk   = (const float*)d_in[6];
    const float* E1 = (const float*)d_in[7];
    const float* W1 = (const float*)d_in[8];
    const float* b1 = (const float*)d_in[9];
    const float* E2 = (const float*)d_in[10];
    const float* W2 = (const float*)d_in[11];
    const float* b2 = (const float*)d_in[12];
    const float* E3 = (const float*)d_in[13];
    const float* W3 = (const float*)d_in[14];
    const float* b3 = (const float*)d_in[15];

    float* hidden = (float*)d_out;
    float* kld_out = hidden + (size_t)NN * DD;
    const int write_kld = (out_size > NN * DD) ? 1 : 0;

    cudaFuncSetAttribute(gemm_h,   cudaFuncAttributeMaxDynamicSharedMemorySize, SMEM_A);
    cudaFuncSetAttribute(gemm_kld, cudaFuncAttributeMaxDynamicSharedMemorySize, SMEM_B);

    const dim3 gg(MT, 4);   // 628 CTAs, N tile 64

    prep_all<<<PB_CONV + PB_WB + PB_C, 256>>>(node_reps, W1, E1, W2, E2, W3, E3,
                                              in_edg, in_msk, out_edg, out_msk);

    gather16<<<(NN + 7) / 8, 256>>>(in_idx, in_msk, out_idx, out_msk);
    gemm_h<<<gg, 256, SMEM_A>>>(node_reps, b1, hidden);

    gather16<<<(NN + 7) / 8, 256>>>(in_idx, in_msk, out_idx, out_msk);
    gemm_kld<<<gg, 256, SMEM_B>>>(b2, b3, kld_out, write_kld);
}